// round 13
// baseline (speedup 1.0000x reference)
#include <cuda_runtime.h>
#include <cstdint>

#define B_ 4
#define C_ 256
#define Q_ 256
#define XD_ 64
#define YD_ 32
#define E_ 64
#define H_ 128
#define ALPHA 0.1f

#define NTILES (B_ * C_ * 4)

typedef unsigned long long u64;

// U stored in fp16 B-fragment (m16n8k16) layout per (b,k): 32KB blocks.
__device__ uint32_t U_scratch[(size_t)B_ * C_ * C_ * E_ / 2];
__device__ float    P_scratch[(size_t)B_ * C_ * H_];
// att prestaged in fp16 A-fragment layout: 32 slices (map,b,Mq) x 8192 u32
__device__ uint32_t ATT_frag[32 * 8192];

// ---------------- helpers (compute_80 features only) ----------
__device__ __forceinline__ uint32_t pack_h2(float lo, float hi) {
    uint32_t r;
    asm("cvt.rn.f16x2.f32 %0, %1, %2;" : "=r"(r) : "f"(hi), "f"(lo));
    return r;
}
__device__ __forceinline__ void mma_f16(float d[4], const uint32_t a[4], const uint32_t b[2]) {
    asm volatile(
        "mma.sync.aligned.m16n8k16.row.col.f32.f16.f16.f32 "
        "{%0,%1,%2,%3}, {%4,%5,%6,%7}, {%8,%9}, {%0,%1,%2,%3};"
        : "+f"(d[0]), "+f"(d[1]), "+f"(d[2]), "+f"(d[3])
        : "r"(a[0]), "r"(a[1]), "r"(a[2]), "r"(a[3]), "r"(b[0]), "r"(b[1]));
}
__device__ __forceinline__ uint32_t smem_u32(const void* p) {
    uint32_t a;
    asm("{ .reg .u64 t; cvta.to.shared.u64 t, %1; cvt.u32.u64 %0, t; }" : "=r"(a) : "l"(p));
    return a;
}
__device__ __forceinline__ void cp_async16(uint32_t s, const void* g) {
    asm volatile("cp.async.cg.shared.global [%0], [%1], 16;" :: "r"(s), "l"(g));
}
__device__ __forceinline__ void cp_commit() { asm volatile("cp.async.commit_group;" ::: "memory"); }
__device__ __forceinline__ void cp_wait0()  { asm volatile("cp.async.wait_group 0;" ::: "memory"); }

#define REGS 136     // MLP fragment strides (skewed; staging scatters remain)
#define TILES 544
#define REGA 128     // attn A fragment strides (dense; cp.async staged)
#define TILEA 512

// ---------------------------------------------------------------------------
// Kernel 1: prep — P (W1 staged in smem once) + att fp16 fragment prestage.
// ---------------------------------------------------------------------------
__global__ void __launch_bounds__(256, 1)
prep_kernel(const float* __restrict__ x, const float* __restrict__ y,
            const float* __restrict__ W1, const float* __restrict__ b1,
            const float* __restrict__ attc, const float* __restrict__ attq) {
    extern __shared__ float ws[];          // [96][128]
    const int t = threadIdx.x;

    for (int i = t; i < 96 * H_; i += 256) ws[i] = W1[i];
    __syncthreads();

    // P: 2 rows per block-iteration
    const int h = t & 127;
    for (int base = blockIdx.x * 2; base < B_ * C_; base += 296) {
        int bj = base + (t >> 7);
        if (bj < B_ * C_) {
            const float* xr = x + (size_t)bj * XD_;
            const float* yr = y + (size_t)bj * YD_;
            float acc = b1[h];
            #pragma unroll 8
            for (int d = 0; d < XD_; d++) acc = fmaf(xr[d], ws[d * H_ + h], acc);
            #pragma unroll 8
            for (int d = 0; d < YD_; d++) acc = fmaf(yr[d], ws[(XD_ + d) * H_ + h], acc);
            P_scratch[(size_t)bj * H_ + h] = acc;
        }
    }

    // att -> fp16 A-fragments (dense 512B tiles), 131072 float4 chunks
    for (int idx = blockIdx.x * 256 + t; idx < 131072; idx += 148 * 256) {
        int j4  = idx & 63;
        int i   = (idx >> 6) & 255;
        int b   = (idx >> 14) & 3;
        int map = idx >> 16;
        const float* att = (map ? attq : attc) + ((size_t)b << 16) + (size_t)i * C_ + j4 * 4;
        float4 v = *(const float4*)att;
        int Mq = i >> 6, i6 = i & 63;
        int mt = i6 >> 4, kt = j4 >> 2;
        int reg = ((i6 >> 3) & 1) | (((j4 >> 1) & 1) << 1);
        int lp  = (i6 & 7) * 4 + (j4 & 1) * 2;
        uint32_t* dst = ATT_frag + (((map * 4 + b) * 4 + Mq) * 8192)
                      + (mt * 16 + kt) * 128 + reg * 32 + lp;
        uint2 w;
        w.x = pack_h2(v.x, v.y);
        w.y = pack_h2(v.z, v.w);
        *(uint2*)dst = w;
    }
}

// ---------------------------------------------------------------------------
// Kernel 2: persistent fp16 tensor-core MLP (unchanged from R11 passing)
// ---------------------------------------------------------------------------
#define W1F 0
#define W2F 16384
#define W3F 49152
#define B2S 65536
#define B3S 66048
#define INF 66304
#define H1F 75008
#define H2F 92416
#define BOUNCE 75008
#define ROWB 144
#define MLP_SMEM_B 109824

__global__ void __launch_bounds__(256, 2)
mlp_tc_kernel(const float* __restrict__ rc,
              const float* __restrict__ W1,
              const float* __restrict__ b2v,
              const float* __restrict__ W2,
              const float* __restrict__ W3,
              const float* __restrict__ b3v) {
    extern __shared__ char smem[];
    const int t    = threadIdx.x;
    const int wid  = t >> 5;
    const int lane = t & 31;
    const int wm   = wid >> 2;
    const int wn   = wid & 3;

    for (int i = t; i < 4096; i += 256) {
        int r = i & 1, ln = (i >> 1) & 31, nt = (i >> 6) & 15, kt = i >> 10;
        int k = kt * 16 + (ln & 3) * 2 + r * 8;
        int n = nt * 8 + (ln >> 2);
        *(uint32_t*)(smem + W1F + i * 4) = pack_h2(W1[(96 + k) * H_ + n], W1[(96 + k + 1) * H_ + n]);
    }
    for (int i = t; i < 8192; i += 256) {
        int r = i & 1, ln = (i >> 1) & 31, nt = (i >> 6) & 15, kt = i >> 10;
        int k = kt * 16 + (ln & 3) * 2 + r * 8;
        int n = nt * 8 + (ln >> 2);
        *(uint32_t*)(smem + W2F + i * 4) = pack_h2(W2[(size_t)k * H_ + n], W2[(size_t)(k + 1) * H_ + n]);
    }
    for (int i = t; i < 4096; i += 256) {
        int r = i & 1, ln = (i >> 1) & 31, nt = (i >> 6) & 7, kt = i >> 9;
        int k = kt * 16 + (ln & 3) * 2 + r * 8;
        int n = nt * 8 + (ln >> 2);
        *(uint32_t*)(smem + W3F + i * 4) = pack_h2(W3[(size_t)k * E_ + n], W3[(size_t)(k + 1) * E_ + n]);
    }
    if (t < 128) *(float*)(smem + B2S + t * 4) = b2v[t];
    if (t < 64)  *(float*)(smem + B3S + t * 4) = b3v[t];

    int prev_bk = -1, prev_j0 = 0;

    for (int tile = blockIdx.x; tile < NTILES; tile += gridDim.x) {
        const int jsub = tile & 3;
        const int bk   = tile >> 2;
        const int b    = bk >> 8;
        const int j0   = jsub * 64;

        if (prev_bk >= 0) {
            uint32_t* Ub = U_scratch + (size_t)prev_bk * 8192;
            #pragma unroll
            for (int w = 0; w < 8; w++) {
                int idx = w * 256 + t;
                int r   = idx & 1;
                int ln  = (idx >> 1) & 31;
                int nt  = (idx >> 6) & 7;
                int ktl = (idx >> 9) & 3;
                int jl  = ktl * 16 + (ln & 3) * 2 + r * 8;
                int e   = nt * 8 + (ln >> 2);
                uint16_t h0 = *(const uint16_t*)(smem + BOUNCE + jl * ROWB + e * 2);
                uint16_t h1 = *(const uint16_t*)(smem + BOUNCE + (jl + 1) * ROWB + e * 2);
                uint32_t word = (uint32_t)h0 | ((uint32_t)h1 << 16);
                int ktg = (prev_j0 >> 4) + ktl;
                Ub[((ktg * 8 + nt) * 32 + ln) * 2 + r] = word;
            }
        }
        {
            const float* rcin = rc + ((size_t)bk * C_ + j0) * E_;
            #pragma unroll
            for (int it = 0; it < 4; it++) {
                int idx = it * 256 + t;
                int r  = idx >> 4;
                int e0 = (idx & 15) * 4;
                float4 v = *(const float4*)&rcin[(size_t)r * E_ + e0];
                int mt = r >> 4, kt = e0 >> 4;
                int reg = ((r >> 3) & 1) | (((e0 >> 3) & 1) << 1);
                int lp  = (r & 7) * 4 + ((e0 & 7) >> 1);
                uint2 w;
                w.x = pack_h2(v.x, v.y);
                w.y = pack_h2(v.z, v.w);
                *(uint2*)(smem + INF + (mt * 4 + kt) * TILES + reg * REGS + lp * 4) = w;
            }
        }
        __syncthreads();

        // ---- Layer 1 ----
        {
            float d[2][4][4];
            const float* Pp = P_scratch + (size_t)(b * C_ + j0) * H_;
            #pragma unroll
            for (int mtl = 0; mtl < 2; mtl++) {
                int r0 = wm * 32 + mtl * 16 + (lane >> 2);
                #pragma unroll
                for (int ntl = 0; ntl < 4; ntl++) {
                    int col = wn * 32 + ntl * 8 + (lane & 3) * 2;
                    float2 p0 = *(const float2*)&Pp[(size_t)r0 * H_ + col];
                    float2 p1 = *(const float2*)&Pp[(size_t)(r0 + 8) * H_ + col];
                    d[mtl][ntl][0] = p0.x; d[mtl][ntl][1] = p0.y;
                    d[mtl][ntl][2] = p1.x; d[mtl][ntl][3] = p1.y;
                }
            }
            #pragma unroll
            for (int kt = 0; kt < 4; kt++) {
                uint32_t a[2][4];
                #pragma unroll
                for (int mtl = 0; mtl < 2; mtl++) {
                    const char* base = smem + INF + ((wm * 2 + mtl) * 4 + kt) * TILES + lane * 4;
                    a[mtl][0] = *(const uint32_t*)(base);
                    a[mtl][1] = *(const uint32_t*)(base + REGS);
                    a[mtl][2] = *(const uint32_t*)(base + 2 * REGS);
                    a[mtl][3] = *(const uint32_t*)(base + 3 * REGS);
                }
                #pragma unroll
                for (int ntl = 0; ntl < 4; ntl++) {
                    int nt = wn * 4 + ntl;
                    uint2 bv = *(const uint2*)(smem + W1F + ((kt * 16 + nt) * 32 + lane) * 8);
                    uint32_t bw[2] = {bv.x, bv.y};
                    #pragma unroll
                    for (int mtl = 0; mtl < 2; mtl++) mma_f16(d[mtl][ntl], a[mtl], bw);
                }
            }
            #pragma unroll
            for (int mtl = 0; mtl < 2; mtl++) {
                int mt2 = wm * 2 + mtl;
                int lp  = (lane >> 2) * 4 + (lane & 3);
                #pragma unroll
                for (int ntl = 0; ntl < 4; ntl++) {
                    int kt2 = wn * 2 + (ntl >> 1);
                    int rlo = (ntl & 1) * 2;
                    const char* fb = smem + H1F + (mt2 * 8 + kt2) * TILES + lp * 4;
                    *(uint32_t*)(fb + rlo * REGS) =
                        pack_h2(fmaxf(d[mtl][ntl][0], 0.0f), fmaxf(d[mtl][ntl][1], 0.0f));
                    *(uint32_t*)(fb + (rlo + 1) * REGS) =
                        pack_h2(fmaxf(d[mtl][ntl][2], 0.0f), fmaxf(d[mtl][ntl][3], 0.0f));
                }
            }
        }
        __syncthreads();

        // ---- Layer 2 ----
        {
            float d[2][4][4];
            #pragma unroll
            for (int mtl = 0; mtl < 2; mtl++)
                #pragma unroll
                for (int ntl = 0; ntl < 4; ntl++) {
                    int col = wn * 32 + ntl * 8 + (lane & 3) * 2;
                    float2 bb = *(const float2*)(smem + B2S + col * 4);
                    d[mtl][ntl][0] = bb.x; d[mtl][ntl][1] = bb.y;
                    d[mtl][ntl][2] = bb.x; d[mtl][ntl][3] = bb.y;
                }
            #pragma unroll
            for (int kt = 0; kt < 8; kt++) {
                uint32_t a[2][4];
                #pragma unroll
                for (int mtl = 0; mtl < 2; mtl++) {
                    const char* base = smem + H1F + ((wm * 2 + mtl) * 8 + kt) * TILES + lane * 4;
                    a[mtl][0] = *(const uint32_t*)(base);
                    a[mtl][1] = *(const uint32_t*)(base + REGS);
                    a[mtl][2] = *(const uint32_t*)(base + 2 * REGS);
                    a[mtl][3] = *(const uint32_t*)(base + 3 * REGS);
                }
                #pragma unroll
                for (int ntl = 0; ntl < 4; ntl++) {
                    int nt = wn * 4 + ntl;
                    uint2 bv = *(const uint2*)(smem + W2F + ((kt * 16 + nt) * 32 + lane) * 8);
                    uint32_t bw[2] = {bv.x, bv.y};
                    #pragma unroll
                    for (int mtl = 0; mtl < 2; mtl++) mma_f16(d[mtl][ntl], a[mtl], bw);
                }
            }
            #pragma unroll
            for (int mtl = 0; mtl < 2; mtl++) {
                int mt2 = wm * 2 + mtl;
                int lp  = (lane >> 2) * 4 + (lane & 3);
                #pragma unroll
                for (int ntl = 0; ntl < 4; ntl++) {
                    int kt2 = wn * 2 + (ntl >> 1);
                    int rlo = (ntl & 1) * 2;
                    const char* fb = smem + H2F + (mt2 * 8 + kt2) * TILES + lp * 4;
                    *(uint32_t*)(fb + rlo * REGS) =
                        pack_h2(fmaxf(d[mtl][ntl][0], 0.0f), fmaxf(d[mtl][ntl][1], 0.0f));
                    *(uint32_t*)(fb + (rlo + 1) * REGS) =
                        pack_h2(fmaxf(d[mtl][ntl][2], 0.0f), fmaxf(d[mtl][ntl][3], 0.0f));
                }
            }
        }
        __syncthreads();

        // ---- Layer 3 ----
        {
            float d[2][2][4];
            #pragma unroll
            for (int mtl = 0; mtl < 2; mtl++)
                #pragma unroll
                for (int ntl = 0; ntl < 2; ntl++) {
                    int e = wn * 16 + ntl * 8 + (lane & 3) * 2;
                    float2 bb = *(const float2*)(smem + B3S + e * 4);
                    d[mtl][ntl][0] = bb.x; d[mtl][ntl][1] = bb.y;
                    d[mtl][ntl][2] = bb.x; d[mtl][ntl][3] = bb.y;
                }
            #pragma unroll
            for (int kt = 0; kt < 8; kt++) {
                uint32_t a[2][4];
                #pragma unroll
                for (int mtl = 0; mtl < 2; mtl++) {
                    const char* base = smem + H2F + ((wm * 2 + mtl) * 8 + kt) * TILES + lane * 4;
                    a[mtl][0] = *(const uint32_t*)(base);
                    a[mtl][1] = *(const uint32_t*)(base + REGS);
                    a[mtl][2] = *(const uint32_t*)(base + 2 * REGS);
                    a[mtl][3] = *(const uint32_t*)(base + 3 * REGS);
                }
                #pragma unroll
                for (int ntl = 0; ntl < 2; ntl++) {
                    int nt = wn * 2 + ntl;
                    uint2 bv = *(const uint2*)(smem + W3F + ((kt * 8 + nt) * 32 + lane) * 8);
                    uint32_t bw[2] = {bv.x, bv.y};
                    #pragma unroll
                    for (int mtl = 0; mtl < 2; mtl++) mma_f16(d[mtl][ntl], a[mtl], bw);
                }
            }
            #pragma unroll
            for (int mtl = 0; mtl < 2; mtl++) {
                int row = wm * 32 + mtl * 16 + (lane >> 2);
                #pragma unroll
                for (int ntl = 0; ntl < 2; ntl++) {
                    int e = wn * 16 + ntl * 8 + (lane & 3) * 2;
                    *(uint32_t*)(smem + BOUNCE + row * ROWB + e * 2) =
                        pack_h2(d[mtl][ntl][0], d[mtl][ntl][1]);
                    *(uint32_t*)(smem + BOUNCE + (row + 8) * ROWB + e * 2) =
                        pack_h2(d[mtl][ntl][2], d[mtl][ntl][3]);
                }
            }
        }
        __syncthreads();

        prev_bk = bk; prev_j0 = j0;
    }

    if (prev_bk >= 0) {
        uint32_t* Ub = U_scratch + (size_t)prev_bk * 8192;
        #pragma unroll
        for (int w = 0; w < 8; w++) {
            int idx = w * 256 + t;
            int r   = idx & 1;
            int ln  = (idx >> 1) & 31;
            int nt  = (idx >> 6) & 7;
            int ktl = (idx >> 9) & 3;
            int jl  = ktl * 16 + (ln & 3) * 2 + r * 8;
            int e   = nt * 8 + (ln >> 2);
            uint16_t h0 = *(const uint16_t*)(smem + BOUNCE + jl * ROWB + e * 2);
            uint16_t h1 = *(const uint16_t*)(smem + BOUNCE + (jl + 1) * ROWB + e * 2);
            uint32_t word = (uint32_t)h0 | ((uint32_t)h1 << 16);
            int ktg = (prev_j0 >> 4) + ktl;
            Ub[((ktg * 8 + nt) * 32 + ln) * 2 + r] = word;
        }
    }
}

// ---------------------------------------------------------------------------
// Kernel 3: fp16 mma attention, warp grid (Wm2, Wn2, Wk2), K-split-2.
// A now cp.async'd from prestaged ATT_frag (dense layout, no cvt/scatter).
// ---------------------------------------------------------------------------
#define AT_A  0
#define AT_B0 32768
#define AT_B1 65536
#define AT_SMEM 98304

__global__ void __launch_bounds__(256, 2)
attn_mma_kernel(const float* __restrict__ rc, const float* __restrict__ rq,
                float* __restrict__ out) {
    extern __shared__ char smem[];
    const uint32_t smem_base = smem_u32(smem);
    const int t = threadIdx.x;
    const int x = blockIdx.x;
    const int kg  = x & 31;
    const int Mq  = (x >> 5) & 3;
    const int map = (x >> 7) & 1;
    const int b   = x >> 8;

    const int wid  = t >> 5;
    const int lane = t & 31;
    const int wk = wid >> 2;
    const int wm = (wid >> 1) & 1;
    const int wn = wid & 1;

    const int k0 = kg * 8;

    // ---- async-stage B(k0) and A (both 32KB), one commit group ----
    {
        const char* srcB = (const char*)(U_scratch + ((size_t)(b * C_ + k0)) * 8192);
        const char* srcA = (const char*)(ATT_frag + ((size_t)((map * 4 + b) * 4 + Mq)) * 8192);
        #pragma unroll
        for (int it = 0; it < 8; it++) {
            int o = (it * 256 + t) * 16;
            cp_async16(smem_base + AT_B0 + o, srcB + o);
        }
        #pragma unroll
        for (int it = 0; it < 8; it++) {
            int o = (it * 256 + t) * 16;
            cp_async16(smem_base + AT_A + o, srcA + o);
        }
        cp_commit();
    }
    cp_wait0();
    __syncthreads();

    float* outbase = out + (map ? (size_t)B_ * C_ * C_ * E_ : 0);
    const float* residbase = map ? rq : rc;

    uint32_t bufoff = AT_B0;
    #pragma unroll 1
    for (int kk = 0; kk < 8; kk++) {
        const int k = k0 + kk;

        if (kk < 7) {
            const char* src = (const char*)(U_scratch + ((size_t)(b * C_ + k + 1)) * 8192);
            uint32_t dst = smem_base + (bufoff ^ (AT_B0 ^ AT_B1));
            #pragma unroll
            for (int it = 0; it < 8; it++) {
                int o = (it * 256 + t) * 16;
                cp_async16(dst + o, src + o);
            }
            cp_commit();
        }

        // ---- mma mainloop: this warp M32 x N32, kt in [wk*8, wk*8+8) ----
        float d[2][4][4];
        #pragma unroll
        for (int i0 = 0; i0 < 2; i0++)
            #pragma unroll
            for (int i1 = 0; i1 < 4; i1++)
                #pragma unroll
                for (int i2 = 0; i2 < 4; i2++) d[i0][i1][i2] = 0.0f;

        #pragma unroll
        for (int kt8 = 0; kt8 < 8; kt8++) {
            const int kt = wk * 8 + kt8;
            uint32_t a[2][4];
            #pragma unroll
            for (int mtl = 0; mtl < 2; mtl++) {
                const char* base = smem + AT_A + ((wm * 2 + mtl) * 16 + kt) * TILEA + lane * 4;
                a[mtl][0] = *(const uint32_t*)(base);
                a[mtl][1] = *(const uint32_t*)(base + REGA);
                a[mtl][2] = *(const uint32_t*)(base + 2 * REGA);
                a[mtl][3] = *(const uint32_t*)(base + 3 * REGA);
            }
            uint32_t bw[4][2];
            #pragma unroll
            for (int ntl = 0; ntl < 4; ntl++) {
                int nt = wn * 4 + ntl;
                uint2 bv = *(const uint2*)(smem + bufoff + ((kt * 8 + nt) * 32 + lane) * 8);
                bw[ntl][0] = bv.x; bw[ntl][1] = bv.y;
            }
            #pragma unroll
            for (int mtl = 0; mtl < 2; mtl++)
                #pragma unroll
                for (int ntl = 0; ntl < 4; ntl++)
                    mma_f16(d[mtl][ntl], a[mtl], bw[ntl]);
        }

        __syncthreads();   // all mainloop reads of B[cur] complete

        // ---- K-split reduction through dead B[cur] buffer ----
        if (wk == 1) {
            char* scr = smem + bufoff + (wid & 3) * 4096;
            #pragma unroll
            for (int mtl = 0; mtl < 2; mtl++)
                #pragma unroll
                for (int ntl = 0; ntl < 4; ntl++)
                    #pragma unroll
                    for (int q = 0; q < 4; q++) {
                        int idx = (mtl * 4 + ntl) * 4 + q;
                        *(float*)(scr + idx * 128 + lane * 4) = d[mtl][ntl][q];
                    }
        }
        __syncthreads();

        if (wk == 0) {
            const char* scr = smem + bufoff + (wid & 3) * 4096;
            #pragma unroll
            for (int mtl = 0; mtl < 2; mtl++)
                #pragma unroll
                for (int ntl = 0; ntl < 4; ntl++)
                    #pragma unroll
                    for (int q = 0; q < 4; q++) {
                        int idx = (mtl * 4 + ntl) * 4 + q;
                        d[mtl][ntl][q] += *(const float*)(scr + idx * 128 + lane * 4);
                    }

            const float* resid = residbase + ((size_t)(b * C_ + k) * C_) * E_;
            float* o = outbase + ((size_t)(b * C_ + k) * C_) * E_;
            #pragma unroll
            for (int mtl = 0; mtl < 2; mtl++) {
                int row = Mq * 64 + wm * 32 + mtl * 16 + (lane >> 2);
                #pragma unroll
                for (int ntl = 0; ntl < 4; ntl++) {
                    int e = wn * 32 + ntl * 8 + (lane & 3) * 2;
                    float2 rA = *(const float2*)&resid[(size_t)row * E_ + e];
                    float2 rB = *(const float2*)&resid[(size_t)(row + 8) * E_ + e];
                    float2 oA, oB;
                    oA.x = rA.x - ALPHA * d[mtl][ntl][0];
                    oA.y = rA.y - ALPHA * d[mtl][ntl][1];
                    oB.x = rB.x - ALPHA * d[mtl][ntl][2];
                    oB.y = rB.y - ALPHA * d[mtl][ntl][3];
                    *(float2*)&o[(size_t)row * E_ + e]       = oA;
                    *(float2*)&o[(size_t)(row + 8) * E_ + e] = oB;
                }
            }
        }

        if (kk < 7) {
            cp_wait0();
            __syncthreads();
            bufoff ^= (AT_B0 ^ AT_B1);
        }
    }
}

// ---------------------------------------------------------------------------
// Launch
// ---------------------------------------------------------------------------
extern "C" void kernel_launch(void* const* d_in, const int* in_sizes, int n_in,
                              void* d_out, int out_size) {
    const float* x    = (const float*)d_in[0];
    const float* y    = (const float*)d_in[1];
    const float* rc   = (const float*)d_in[2];
    const float* rq   = (const float*)d_in[3];
    const float* attc = (const float*)d_in[4];
    const float* attq = (const float*)d_in[5];
    const float* W1   = (const float*)d_in[6];
    const float* b1   = (const float*)d_in[7];
    const float* W2   = (const float*)d_in[8];
    const float* b2   = (const float*)d_in[9];
    const float* W3   = (const float*)d_in[10];
    const float* b3   = (const float*)d_in[11];
    float* out = (float*)d_out;

    const int PREP_SMEM = 96 * H_ * (int)sizeof(float);   // 48KB+... = 49152

    cudaFuncSetAttribute(prep_kernel,     cudaFuncAttributeMaxDynamicSharedMemorySize, PREP_SMEM);
    cudaFuncSetAttribute(mlp_tc_kernel,   cudaFuncAttributeMaxDynamicSharedMemorySize, MLP_SMEM_B);
    cudaFuncSetAttribute(attn_mma_kernel, cudaFuncAttributeMaxDynamicSharedMemorySize, AT_SMEM);

    prep_kernel<<<148, 256, PREP_SMEM>>>(x, y, W1, b1, attc, attq);
    mlp_tc_kernel<<<296, 256, MLP_SMEM_B>>>(rc, W1, b2, W2, W3, b3);
    attn_mma_kernel<<<1024, 256, AT_SMEM>>>(rc, rq, out);
}

// round 16
// speedup vs baseline: 1.0517x; 1.0517x over previous
#include <cuda_runtime.h>
#include <cstdint>

#define B_ 4
#define C_ 256
#define Q_ 256
#define XD_ 64
#define YD_ 32
#define E_ 64
#define H_ 128
#define ALPHA 0.1f

#define NTILES (B_ * C_ * 4)

typedef unsigned long long u64;

// U stored in fp16 B-fragment (m16n8k16) layout per (b,k): 32KB blocks.
__device__ uint32_t U_scratch[(size_t)B_ * C_ * C_ * E_ / 2];
__device__ float    P_scratch[(size_t)B_ * C_ * H_];
// att prestaged in fp16 A-fragment layout: 32 slices (map,b,Mq) x 8192 u32
__device__ uint32_t ATT_frag[32 * 8192];

// ---------------- helpers (compute_80 features only) ----------
__device__ __forceinline__ uint32_t pack_h2(float lo, float hi) {
    uint32_t r;
    asm("cvt.rn.f16x2.f32 %0, %1, %2;" : "=r"(r) : "f"(hi), "f"(lo));
    return r;
}
__device__ __forceinline__ void mma_f16(float d[4], const uint32_t a[4], const uint32_t b[2]) {
    asm volatile(
        "mma.sync.aligned.m16n8k16.row.col.f32.f16.f16.f32 "
        "{%0,%1,%2,%3}, {%4,%5,%6,%7}, {%8,%9}, {%0,%1,%2,%3};"
        : "+f"(d[0]), "+f"(d[1]), "+f"(d[2]), "+f"(d[3])
        : "r"(a[0]), "r"(a[1]), "r"(a[2]), "r"(a[3]), "r"(b[0]), "r"(b[1]));
}
__device__ __forceinline__ uint32_t smem_u32(const void* p) {
    uint32_t a;
    asm("{ .reg .u64 t; cvta.to.shared.u64 t, %1; cvt.u32.u64 %0, t; }" : "=r"(a) : "l"(p));
    return a;
}
__device__ __forceinline__ void cp_async16(uint32_t s, const void* g) {
    asm volatile("cp.async.cg.shared.global [%0], [%1], 16;" :: "r"(s), "l"(g));
}
__device__ __forceinline__ void cp_commit() { asm volatile("cp.async.commit_group;" ::: "memory"); }
__device__ __forceinline__ void cp_wait0()  { asm volatile("cp.async.wait_group 0;" ::: "memory"); }

#define REGS 136     // MLP fragment strides (skewed; staging scatters remain)
#define TILES 544
#define REGA 128     // attn A fragment strides (dense; cp.async staged)
#define TILEA 512

// ---------------------------------------------------------------------------
// Kernel 1: P[b,j,h] (simple, measured-fast) + att fp16 fragment conversion
// folded in (exactly 1 float4 chunk per thread: 1024 blocks x 128 threads).
// ---------------------------------------------------------------------------
__global__ void p_kernel(const float* __restrict__ x, const float* __restrict__ y,
                         const float* __restrict__ W1, const float* __restrict__ b1,
                         const float* __restrict__ attc, const float* __restrict__ attq) {
    int bj = blockIdx.x;
    int h  = threadIdx.x;
    const float* xr = x + (size_t)bj * XD_;
    const float* yr = y + (size_t)bj * YD_;
    float acc = b1[h];
    #pragma unroll 8
    for (int d = 0; d < XD_; d++) acc = fmaf(xr[d], W1[d * H_ + h], acc);
    #pragma unroll 8
    for (int d = 0; d < YD_; d++) acc = fmaf(yr[d], W1[(XD_ + d) * H_ + h], acc);
    P_scratch[(size_t)bj * H_ + h] = acc;

    // ---- att -> fp16 A-fragments: one float4 chunk per thread ----
    {
        int idx = blockIdx.x * 128 + threadIdx.x;     // 0..131071
        int j4  = idx & 63;
        int i   = (idx >> 6) & 255;
        int b   = (idx >> 14) & 3;
        int map = idx >> 16;
        const float* att = (map ? attq : attc) + ((size_t)b << 16) + (size_t)i * C_ + j4 * 4;
        float4 v = *(const float4*)att;
        int Mq = i >> 6, i6 = i & 63;
        int mt = i6 >> 4, kt = j4 >> 2;
        int reg = ((i6 >> 3) & 1) | (((j4 >> 1) & 1) << 1);
        int lp  = (i6 & 7) * 4 + (j4 & 1) * 2;
        uint32_t* dst = ATT_frag + (((map * 4 + b) * 4 + Mq) * 8192)
                      + (mt * 16 + kt) * 128 + reg * 32 + lp;
        uint2 w;
        w.x = pack_h2(v.x, v.y);
        w.y = pack_h2(v.z, v.w);
        *(uint2*)dst = w;
    }
}

// ---------------------------------------------------------------------------
// Kernel 2: persistent fp16 tensor-core MLP (unchanged from R11 passing)
// ---------------------------------------------------------------------------
#define W1F 0
#define W2F 16384
#define W3F 49152
#define B2S 65536
#define B3S 66048
#define INF 66304
#define H1F 75008
#define H2F 92416
#define BOUNCE 75008
#define ROWB 144
#define MLP_SMEM_B 109824

__global__ void __launch_bounds__(256, 2)
mlp_tc_kernel(const float* __restrict__ rc,
              const float* __restrict__ W1,
              const float* __restrict__ b2v,
              const float* __restrict__ W2,
              const float* __restrict__ W3,
              const float* __restrict__ b3v) {
    extern __shared__ char smem[];
    const int t    = threadIdx.x;
    const int wid  = t >> 5;
    const int lane = t & 31;
    const int wm   = wid >> 2;
    const int wn   = wid & 3;

    for (int i = t; i < 4096; i += 256) {
        int r = i & 1, ln = (i >> 1) & 31, nt = (i >> 6) & 15, kt = i >> 10;
        int k = kt * 16 + (ln & 3) * 2 + r * 8;
        int n = nt * 8 + (ln >> 2);
        *(uint32_t*)(smem + W1F + i * 4) = pack_h2(W1[(96 + k) * H_ + n], W1[(96 + k + 1) * H_ + n]);
    }
    for (int i = t; i < 8192; i += 256) {
        int r = i & 1, ln = (i >> 1) & 31, nt = (i >> 6) & 15, kt = i >> 10;
        int k = kt * 16 + (ln & 3) * 2 + r * 8;
        int n = nt * 8 + (ln >> 2);
        *(uint32_t*)(smem + W2F + i * 4) = pack_h2(W2[(size_t)k * H_ + n], W2[(size_t)(k + 1) * H_ + n]);
    }
    for (int i = t; i < 4096; i += 256) {
        int r = i & 1, ln = (i >> 1) & 31, nt = (i >> 6) & 7, kt = i >> 9;
        int k = kt * 16 + (ln & 3) * 2 + r * 8;
        int n = nt * 8 + (ln >> 2);
        *(uint32_t*)(smem + W3F + i * 4) = pack_h2(W3[(size_t)k * E_ + n], W3[(size_t)(k + 1) * E_ + n]);
    }
    if (t < 128) *(float*)(smem + B2S + t * 4) = b2v[t];
    if (t < 64)  *(float*)(smem + B3S + t * 4) = b3v[t];

    int prev_bk = -1, prev_j0 = 0;

    for (int tile = blockIdx.x; tile < NTILES; tile += gridDim.x) {
        const int jsub = tile & 3;
        const int bk   = tile >> 2;
        const int b    = bk >> 8;
        const int j0   = jsub * 64;

        if (prev_bk >= 0) {
            uint32_t* Ub = U_scratch + (size_t)prev_bk * 8192;
            #pragma unroll
            for (int w = 0; w < 8; w++) {
                int idx = w * 256 + t;
                int r   = idx & 1;
                int ln  = (idx >> 1) & 31;
                int nt  = (idx >> 6) & 7;
                int ktl = (idx >> 9) & 3;
                int jl  = ktl * 16 + (ln & 3) * 2 + r * 8;
                int e   = nt * 8 + (ln >> 2);
                uint16_t h0 = *(const uint16_t*)(smem + BOUNCE + jl * ROWB + e * 2);
                uint16_t h1 = *(const uint16_t*)(smem + BOUNCE + (jl + 1) * ROWB + e * 2);
                uint32_t word = (uint32_t)h0 | ((uint32_t)h1 << 16);
                int ktg = (prev_j0 >> 4) + ktl;
                Ub[((ktg * 8 + nt) * 32 + ln) * 2 + r] = word;
            }
        }
        {
            const float* rcin = rc + ((size_t)bk * C_ + j0) * E_;
            #pragma unroll
            for (int it = 0; it < 4; it++) {
                int idx = it * 256 + t;
                int r  = idx >> 4;
                int e0 = (idx & 15) * 4;
                float4 v = *(const float4*)&rcin[(size_t)r * E_ + e0];
                int mt = r >> 4, kt = e0 >> 4;
                int reg = ((r >> 3) & 1) | (((e0 >> 3) & 1) << 1);
                int lp  = (r & 7) * 4 + ((e0 & 7) >> 1);
                uint2 w;
                w.x = pack_h2(v.x, v.y);
                w.y = pack_h2(v.z, v.w);
                *(uint2*)(smem + INF + (mt * 4 + kt) * TILES + reg * REGS + lp * 4) = w;
            }
        }
        __syncthreads();

        // ---- Layer 1 ----
        {
            float d[2][4][4];
            const float* Pp = P_scratch + (size_t)(b * C_ + j0) * H_;
            #pragma unroll
            for (int mtl = 0; mtl < 2; mtl++) {
                int r0 = wm * 32 + mtl * 16 + (lane >> 2);
                #pragma unroll
                for (int ntl = 0; ntl < 4; ntl++) {
                    int col = wn * 32 + ntl * 8 + (lane & 3) * 2;
                    float2 p0 = *(const float2*)&Pp[(size_t)r0 * H_ + col];
                    float2 p1 = *(const float2*)&Pp[(size_t)(r0 + 8) * H_ + col];
                    d[mtl][ntl][0] = p0.x; d[mtl][ntl][1] = p0.y;
                    d[mtl][ntl][2] = p1.x; d[mtl][ntl][3] = p1.y;
                }
            }
            #pragma unroll
            for (int kt = 0; kt < 4; kt++) {
                uint32_t a[2][4];
                #pragma unroll
                for (int mtl = 0; mtl < 2; mtl++) {
                    const char* base = smem + INF + ((wm * 2 + mtl) * 4 + kt) * TILES + lane * 4;
                    a[mtl][0] = *(const uint32_t*)(base);
                    a[mtl][1] = *(const uint32_t*)(base + REGS);
                    a[mtl][2] = *(const uint32_t*)(base + 2 * REGS);
                    a[mtl][3] = *(const uint32_t*)(base + 3 * REGS);
                }
                #pragma unroll
                for (int ntl = 0; ntl < 4; ntl++) {
                    int nt = wn * 4 + ntl;
                    uint2 bv = *(const uint2*)(smem + W1F + ((kt * 16 + nt) * 32 + lane) * 8);
                    uint32_t bw[2] = {bv.x, bv.y};
                    #pragma unroll
                    for (int mtl = 0; mtl < 2; mtl++) mma_f16(d[mtl][ntl], a[mtl], bw);
                }
            }
            #pragma unroll
            for (int mtl = 0; mtl < 2; mtl++) {
                int mt2 = wm * 2 + mtl;
                int lp  = (lane >> 2) * 4 + (lane & 3);
                #pragma unroll
                for (int ntl = 0; ntl < 4; ntl++) {
                    int kt2 = wn * 2 + (ntl >> 1);
                    int rlo = (ntl & 1) * 2;
                    const char* fb = smem + H1F + (mt2 * 8 + kt2) * TILES + lp * 4;
                    *(uint32_t*)(fb + rlo * REGS) =
                        pack_h2(fmaxf(d[mtl][ntl][0], 0.0f), fmaxf(d[mtl][ntl][1], 0.0f));
                    *(uint32_t*)(fb + (rlo + 1) * REGS) =
                        pack_h2(fmaxf(d[mtl][ntl][2], 0.0f), fmaxf(d[mtl][ntl][3], 0.0f));
                }
            }
        }
        __syncthreads();

        // ---- Layer 2 ----
        {
            float d[2][4][4];
            #pragma unroll
            for (int mtl = 0; mtl < 2; mtl++)
                #pragma unroll
                for (int ntl = 0; ntl < 4; ntl++) {
                    int col = wn * 32 + ntl * 8 + (lane & 3) * 2;
                    float2 bb = *(const float2*)(smem + B2S + col * 4);
                    d[mtl][ntl][0] = bb.x; d[mtl][ntl][1] = bb.y;
                    d[mtl][ntl][2] = bb.x; d[mtl][ntl][3] = bb.y;
                }
            #pragma unroll
            for (int kt = 0; kt < 8; kt++) {
                uint32_t a[2][4];
                #pragma unroll
                for (int mtl = 0; mtl < 2; mtl++) {
                    const char* base = smem + H1F + ((wm * 2 + mtl) * 8 + kt) * TILES + lane * 4;
                    a[mtl][0] = *(const uint32_t*)(base);
                    a[mtl][1] = *(const uint32_t*)(base + REGS);
                    a[mtl][2] = *(const uint32_t*)(base + 2 * REGS);
                    a[mtl][3] = *(const uint32_t*)(base + 3 * REGS);
                }
                #pragma unroll
                for (int ntl = 0; ntl < 4; ntl++) {
                    int nt = wn * 4 + ntl;
                    uint2 bv = *(const uint2*)(smem + W2F + ((kt * 16 + nt) * 32 + lane) * 8);
                    uint32_t bw[2] = {bv.x, bv.y};
                    #pragma unroll
                    for (int mtl = 0; mtl < 2; mtl++) mma_f16(d[mtl][ntl], a[mtl], bw);
                }
            }
            #pragma unroll
            for (int mtl = 0; mtl < 2; mtl++) {
                int mt2 = wm * 2 + mtl;
                int lp  = (lane >> 2) * 4 + (lane & 3);
                #pragma unroll
                for (int ntl = 0; ntl < 4; ntl++) {
                    int kt2 = wn * 2 + (ntl >> 1);
                    int rlo = (ntl & 1) * 2;
                    const char* fb = smem + H2F + (mt2 * 8 + kt2) * TILES + lp * 4;
                    *(uint32_t*)(fb + rlo * REGS) =
                        pack_h2(fmaxf(d[mtl][ntl][0], 0.0f), fmaxf(d[mtl][ntl][1], 0.0f));
                    *(uint32_t*)(fb + (rlo + 1) * REGS) =
                        pack_h2(fmaxf(d[mtl][ntl][2], 0.0f), fmaxf(d[mtl][ntl][3], 0.0f));
                }
            }
        }
        __syncthreads();

        // ---- Layer 3 ----
        {
            float d[2][2][4];
            #pragma unroll
            for (int mtl = 0; mtl < 2; mtl++)
                #pragma unroll
                for (int ntl = 0; ntl < 2; ntl++) {
                    int e = wn * 16 + ntl * 8 + (lane & 3) * 2;
                    float2 bb = *(const float2*)(smem + B3S + e * 4);
                    d[mtl][ntl][0] = bb.x; d[mtl][ntl][1] = bb.y;
                    d[mtl][ntl][2] = bb.x; d[mtl][ntl][3] = bb.y;
                }
            #pragma unroll
            for (int kt = 0; kt < 8; kt++) {
                uint32_t a[2][4];
                #pragma unroll
                for (int mtl = 0; mtl < 2; mtl++) {
                    const char* base = smem + H2F + ((wm * 2 + mtl) * 8 + kt) * TILES + lane * 4;
                    a[mtl][0] = *(const uint32_t*)(base);
                    a[mtl][1] = *(const uint32_t*)(base + REGS);
                    a[mtl][2] = *(const uint32_t*)(base + 2 * REGS);
                    a[mtl][3] = *(const uint32_t*)(base + 3 * REGS);
                }
                #pragma unroll
                for (int ntl = 0; ntl < 2; ntl++) {
                    int nt = wn * 2 + ntl;
                    uint2 bv = *(const uint2*)(smem + W3F + ((kt * 8 + nt) * 32 + lane) * 8);
                    uint32_t bw[2] = {bv.x, bv.y};
                    #pragma unroll
                    for (int mtl = 0; mtl < 2; mtl++) mma_f16(d[mtl][ntl], a[mtl], bw);
                }
            }
            #pragma unroll
            for (int mtl = 0; mtl < 2; mtl++) {
                int row = wm * 32 + mtl * 16 + (lane >> 2);
                #pragma unroll
                for (int ntl = 0; ntl < 2; ntl++) {
                    int e = wn * 16 + ntl * 8 + (lane & 3) * 2;
                    *(uint32_t*)(smem + BOUNCE + row * ROWB + e * 2) =
                        pack_h2(d[mtl][ntl][0], d[mtl][ntl][1]);
                    *(uint32_t*)(smem + BOUNCE + (row + 8) * ROWB + e * 2) =
                        pack_h2(d[mtl][ntl][2], d[mtl][ntl][3]);
                }
            }
        }
        __syncthreads();

        prev_bk = bk; prev_j0 = j0;
    }

    if (prev_bk >= 0) {
        uint32_t* Ub = U_scratch + (size_t)prev_bk * 8192;
        #pragma unroll
        for (int w = 0; w < 8; w++) {
            int idx = w * 256 + t;
            int r   = idx & 1;
            int ln  = (idx >> 1) & 31;
            int nt  = (idx >> 6) & 7;
            int ktl = (idx >> 9) & 3;
            int jl  = ktl * 16 + (ln & 3) * 2 + r * 8;
            int e   = nt * 8 + (ln >> 2);
            uint16_t h0 = *(const uint16_t*)(smem + BOUNCE + jl * ROWB + e * 2);
            uint16_t h1 = *(const uint16_t*)(smem + BOUNCE + (jl + 1) * ROWB + e * 2);
            uint32_t word = (uint32_t)h0 | ((uint32_t)h1 << 16);
            int ktg = (prev_j0 >> 4) + ktl;
            Ub[((ktg * 8 + nt) * 32 + ln) * 2 + r] = word;
        }
    }
}

// ---------------------------------------------------------------------------
// Kernel 3: fp16 mma attention, warp grid (Wm2, Wn2, Wk2), K-split-2.
// A cp.async'd from prestaged ATT_frag (dense layout, no cvt/scatter).
// ---------------------------------------------------------------------------
#define AT_A  0
#define AT_B0 32768
#define AT_B1 65536
#define AT_SMEM 98304

__global__ void __launch_bounds__(256, 2)
attn_mma_kernel(const float* __restrict__ rc, const float* __restrict__ rq,
                float* __restrict__ out) {
    extern __shared__ char smem[];
    const uint32_t smem_base = smem_u32(smem);
    const int t = threadIdx.x;
    const int x = blockIdx.x;
    const int kg  = x & 31;
    const int Mq  = (x >> 5) & 3;
    const int map = (x >> 7) & 1;
    const int b   = x >> 8;

    const int wid  = t >> 5;
    const int lane = t & 31;
    const int wk = wid >> 2;
    const int wm = (wid >> 1) & 1;
    const int wn = wid & 1;

    const int k0 = kg * 8;

    // ---- async-stage B(k0) and A (both 32KB), one commit group ----
    {
        const char* srcB = (const char*)(U_scratch + ((size_t)(b * C_ + k0)) * 8192);
        const char* srcA = (const char*)(ATT_frag + ((size_t)((map * 4 + b) * 4 + Mq)) * 8192);
        #pragma unroll
        for (int it = 0; it < 8; it++) {
            int o = (it * 256 + t) * 16;
            cp_async16(smem_base + AT_B0 + o, srcB + o);
        }
        #pragma unroll
        for (int it = 0; it < 8; it++) {
            int o = (it * 256 + t) * 16;
            cp_async16(smem_base + AT_A + o, srcA + o);
        }
        cp_commit();
    }
    cp_wait0();
    __syncthreads();

    float* outbase = out + (map ? (size_t)B_ * C_ * C_ * E_ : 0);
    const float* residbase = map ? rq : rc;

    uint32_t bufoff = AT_B0;
    #pragma unroll 1
    for (int kk = 0; kk < 8; kk++) {
        const int k = k0 + kk;

        if (kk < 7) {
            const char* src = (const char*)(U_scratch + ((size_t)(b * C_ + k + 1)) * 8192);
            uint32_t dst = smem_base + (bufoff ^ (AT_B0 ^ AT_B1));
            #pragma unroll
            for (int it = 0; it < 8; it++) {
                int o = (it * 256 + t) * 16;
                cp_async16(dst + o, src + o);
            }
            cp_commit();
        }

        // ---- mma mainloop: this warp M32 x N32, kt in [wk*8, wk*8+8) ----
        float d[2][4][4];
        #pragma unroll
        for (int i0 = 0; i0 < 2; i0++)
            #pragma unroll
            for (int i1 = 0; i1 < 4; i1++)
                #pragma unroll
                for (int i2 = 0; i2 < 4; i2++) d[i0][i1][i2] = 0.0f;

        #pragma unroll
        for (int kt8 = 0; kt8 < 8; kt8++) {
            const int kt = wk * 8 + kt8;
            uint32_t a[2][4];
            #pragma unroll
            for (int mtl = 0; mtl < 2; mtl++) {
                const char* base = smem + AT_A + ((wm * 2 + mtl) * 16 + kt) * TILEA + lane * 4;
                a[mtl][0] = *(const uint32_t*)(base);
                a[mtl][1] = *(const uint32_t*)(base + REGA);
                a[mtl][2] = *(const uint32_t*)(base + 2 * REGA);
                a[mtl][3] = *(const uint32_t*)(base + 3 * REGA);
            }
            uint32_t bw[4][2];
            #pragma unroll
            for (int ntl = 0; ntl < 4; ntl++) {
                int nt = wn * 4 + ntl;
                uint2 bv = *(const uint2*)(smem + bufoff + ((kt * 8 + nt) * 32 + lane) * 8);
                bw[ntl][0] = bv.x; bw[ntl][1] = bv.y;
            }
            #pragma unroll
            for (int mtl = 0; mtl < 2; mtl++)
                #pragma unroll
                for (int ntl = 0; ntl < 4; ntl++)
                    mma_f16(d[mtl][ntl], a[mtl], bw[ntl]);
        }

        __syncthreads();   // all mainloop reads of B[cur] complete

        // ---- K-split reduction through dead B[cur] buffer ----
        if (wk == 1) {
            char* scr = smem + bufoff + (wid & 3) * 4096;
            #pragma unroll
            for (int mtl = 0; mtl < 2; mtl++)
                #pragma unroll
                for (int ntl = 0; ntl < 4; ntl++)
                    #pragma unroll
                    for (int q = 0; q < 4; q++) {
                        int idx = (mtl * 4 + ntl) * 4 + q;
                        *(float*)(scr + idx * 128 + lane * 4) = d[mtl][ntl][q];
                    }
        }
        __syncthreads();

        if (wk == 0) {
            const char* scr = smem + bufoff + (wid & 3) * 4096;
            #pragma unroll
            for (int mtl = 0; mtl < 2; mtl++)
                #pragma unroll
                for (int ntl = 0; ntl < 4; ntl++)
                    #pragma unroll
                    for (int q = 0; q < 4; q++) {
                        int idx = (mtl * 4 + ntl) * 4 + q;
                        d[mtl][ntl][q] += *(const float*)(scr + idx * 128 + lane * 4);
                    }

            const float* resid = residbase + ((size_t)(b * C_ + k) * C_) * E_;
            float* o = outbase + ((size_t)(b * C_ + k) * C_) * E_;
            #pragma unroll
            for (int mtl = 0; mtl < 2; mtl++) {
                int row = Mq * 64 + wm * 32 + mtl * 16 + (lane >> 2);
                #pragma unroll
                for (int ntl = 0; ntl < 4; ntl++) {
                    int e = wn * 32 + ntl * 8 + (lane & 3) * 2;
                    float2 rA = *(const float2*)&resid[(size_t)row * E_ + e];
                    float2 rB = *(const float2*)&resid[(size_t)(row + 8) * E_ + e];
                    float2 oA, oB;
                    oA.x = rA.x - ALPHA * d[mtl][ntl][0];
                    oA.y = rA.y - ALPHA * d[mtl][ntl][1];
                    oB.x = rB.x - ALPHA * d[mtl][ntl][2];
                    oB.y = rB.y - ALPHA * d[mtl][ntl][3];
                    *(float2*)&o[(size_t)row * E_ + e]       = oA;
                    *(float2*)&o[(size_t)(row + 8) * E_ + e] = oB;
                }
            }
        }

        if (kk < 7) {
            cp_wait0();
            __syncthreads();
            bufoff ^= (AT_B0 ^ AT_B1);
        }
    }
}

// ---------------------------------------------------------------------------
// Launch
// ---------------------------------------------------------------------------
extern "C" void kernel_launch(void* const* d_in, const int* in_sizes, int n_in,
                              void* d_out, int out_size) {
    const float* x    = (const float*)d_in[0];
    const float* y    = (const float*)d_in[1];
    const float* rc   = (const float*)d_in[2];
    const float* rq   = (const float*)d_in[3];
    const float* attc = (const float*)d_in[4];
    const float* attq = (const float*)d_in[5];
    const float* W1   = (const float*)d_in[6];
    const float* b1   = (const float*)d_in[7];
    const float* W2   = (const float*)d_in[8];
    const float* b2   = (const float*)d_in[9];
    const float* W3   = (const float*)d_in[10];
    const float* b3   = (const float*)d_in[11];
    float* out = (float*)d_out;

    cudaFuncSetAttribute(mlp_tc_kernel,   cudaFuncAttributeMaxDynamicSharedMemorySize, MLP_SMEM_B);
    cudaFuncSetAttribute(attn_mma_kernel, cudaFuncAttributeMaxDynamicSharedMemorySize, AT_SMEM);

    p_kernel<<<B_ * C_, H_>>>(x, y, W1, b1, attc, attq);
    mlp_tc_kernel<<<296, 256, MLP_SMEM_B>>>(rc, W1, b2, W2, W3, b3);
    attn_mma_kernel<<<1024, 256, AT_SMEM>>>(rc, rq, out);
}

// round 17
// speedup vs baseline: 1.1153x; 1.0605x over previous
#include <cuda_runtime.h>
#include <cstdint>

#define B_ 4
#define C_ 256
#define Q_ 256
#define XD_ 64
#define YD_ 32
#define E_ 64
#define H_ 128
#define ALPHA 0.1f

#define NTILES (B_ * C_ * 4)

typedef unsigned long long u64;

// U stored in fp16 B-fragment (m16n8k16) layout per (b,k): 32KB blocks.
__device__ uint32_t U_scratch[(size_t)B_ * C_ * C_ * E_ / 2];
__device__ float    P_scratch[(size_t)B_ * C_ * H_];
// att prestaged in fp16 A-fragment layout: 32 slices (map,b,Mq) x 8192 u32
__device__ uint32_t ATT_frag[32 * 8192];

// ---------------- helpers (compute_80 features only) ----------
__device__ __forceinline__ uint32_t pack_h2(float lo, float hi) {
    uint32_t r;
    asm("cvt.rn.f16x2.f32 %0, %1, %2;" : "=r"(r) : "f"(hi), "f"(lo));
    return r;
}
__device__ __forceinline__ void mma_f16(float d[4], const uint32_t a[4], const uint32_t b[2]) {
    asm volatile(
        "mma.sync.aligned.m16n8k16.row.col.f32.f16.f16.f32 "
        "{%0,%1,%2,%3}, {%4,%5,%6,%7}, {%8,%9}, {%0,%1,%2,%3};"
        : "+f"(d[0]), "+f"(d[1]), "+f"(d[2]), "+f"(d[3])
        : "r"(a[0]), "r"(a[1]), "r"(a[2]), "r"(a[3]), "r"(b[0]), "r"(b[1]));
}
__device__ __forceinline__ uint32_t smem_u32(const void* p) {
    uint32_t a;
    asm("{ .reg .u64 t; cvta.to.shared.u64 t, %1; cvt.u32.u64 %0, t; }" : "=r"(a) : "l"(p));
    return a;
}
__device__ __forceinline__ void cp_async16(uint32_t s, const void* g) {
    asm volatile("cp.async.cg.shared.global [%0], [%1], 16;" :: "r"(s), "l"(g));
}
__device__ __forceinline__ void cp_commit() { asm volatile("cp.async.commit_group;" ::: "memory"); }
__device__ __forceinline__ void cp_wait0()  { asm volatile("cp.async.wait_group 0;" ::: "memory"); }

#define REGS 136     // MLP fragment strides (skewed; staging scatters remain)
#define TILES 544
#define REGA 128     // attn A fragment strides (dense; cp.async staged)
#define TILEA 512

// ---------------------------------------------------------------------------
// Kernel 1: P[b,j,h] (simple, measured-fast) + att fp16 fragment conversion
// folded in (exactly 1 float4 chunk per thread: 1024 blocks x 128 threads).
// ---------------------------------------------------------------------------
__global__ void p_kernel(const float* __restrict__ x, const float* __restrict__ y,
                         const float* __restrict__ W1, const float* __restrict__ b1,
                         const float* __restrict__ attc, const float* __restrict__ attq) {
    int bj = blockIdx.x;
    int h  = threadIdx.x;
    const float* xr = x + (size_t)bj * XD_;
    const float* yr = y + (size_t)bj * YD_;
    float acc = b1[h];
    #pragma unroll 8
    for (int d = 0; d < XD_; d++) acc = fmaf(xr[d], W1[d * H_ + h], acc);
    #pragma unroll 8
    for (int d = 0; d < YD_; d++) acc = fmaf(yr[d], W1[(XD_ + d) * H_ + h], acc);
    P_scratch[(size_t)bj * H_ + h] = acc;

    // ---- att -> fp16 A-fragments: one float4 chunk per thread ----
    {
        int idx = blockIdx.x * 128 + threadIdx.x;     // 0..131071
        int j4  = idx & 63;
        int i   = (idx >> 6) & 255;
        int b   = (idx >> 14) & 3;
        int map = idx >> 16;
        const float* att = (map ? attq : attc) + ((size_t)b << 16) + (size_t)i * C_ + j4 * 4;
        float4 v = *(const float4*)att;
        int Mq = i >> 6, i6 = i & 63;
        int mt = i6 >> 4, kt = j4 >> 2;
        int reg = ((i6 >> 3) & 1) | (((j4 >> 1) & 1) << 1);
        int lp  = (i6 & 7) * 4 + (j4 & 1) * 2;
        uint32_t* dst = ATT_frag + (((map * 4 + b) * 4 + Mq) * 8192)
                      + (mt * 16 + kt) * 128 + reg * 32 + lp;
        uint2 w;
        w.x = pack_h2(v.x, v.y);
        w.y = pack_h2(v.z, v.w);
        *(uint2*)dst = w;
    }
}

// ---------------------------------------------------------------------------
// Kernel 2: persistent fp16 tensor-core MLP (unchanged from R16 passing)
// ---------------------------------------------------------------------------
#define W1F 0
#define W2F 16384
#define W3F 49152
#define B2S 65536
#define B3S 66048
#define INF 66304
#define H1F 75008
#define H2F 92416
#define BOUNCE 75008
#define ROWB 144
#define MLP_SMEM_B 109824

__global__ void __launch_bounds__(256, 2)
mlp_tc_kernel(const float* __restrict__ rc,
              const float* __restrict__ W1,
              const float* __restrict__ b2v,
              const float* __restrict__ W2,
              const float* __restrict__ W3,
              const float* __restrict__ b3v) {
    extern __shared__ char smem[];
    const int t    = threadIdx.x;
    const int wid  = t >> 5;
    const int lane = t & 31;
    const int wm   = wid >> 2;
    const int wn   = wid & 3;

    for (int i = t; i < 4096; i += 256) {
        int r = i & 1, ln = (i >> 1) & 31, nt = (i >> 6) & 15, kt = i >> 10;
        int k = kt * 16 + (ln & 3) * 2 + r * 8;
        int n = nt * 8 + (ln >> 2);
        *(uint32_t*)(smem + W1F + i * 4) = pack_h2(W1[(96 + k) * H_ + n], W1[(96 + k + 1) * H_ + n]);
    }
    for (int i = t; i < 8192; i += 256) {
        int r = i & 1, ln = (i >> 1) & 31, nt = (i >> 6) & 15, kt = i >> 10;
        int k = kt * 16 + (ln & 3) * 2 + r * 8;
        int n = nt * 8 + (ln >> 2);
        *(uint32_t*)(smem + W2F + i * 4) = pack_h2(W2[(size_t)k * H_ + n], W2[(size_t)(k + 1) * H_ + n]);
    }
    for (int i = t; i < 4096; i += 256) {
        int r = i & 1, ln = (i >> 1) & 31, nt = (i >> 6) & 7, kt = i >> 9;
        int k = kt * 16 + (ln & 3) * 2 + r * 8;
        int n = nt * 8 + (ln >> 2);
        *(uint32_t*)(smem + W3F + i * 4) = pack_h2(W3[(size_t)k * E_ + n], W3[(size_t)(k + 1) * E_ + n]);
    }
    if (t < 128) *(float*)(smem + B2S + t * 4) = b2v[t];
    if (t < 64)  *(float*)(smem + B3S + t * 4) = b3v[t];

    int prev_bk = -1, prev_j0 = 0;

    for (int tile = blockIdx.x; tile < NTILES; tile += gridDim.x) {
        const int jsub = tile & 3;
        const int bk   = tile >> 2;
        const int b    = bk >> 8;
        const int j0   = jsub * 64;

        if (prev_bk >= 0) {
            uint32_t* Ub = U_scratch + (size_t)prev_bk * 8192;
            #pragma unroll
            for (int w = 0; w < 8; w++) {
                int idx = w * 256 + t;
                int r   = idx & 1;
                int ln  = (idx >> 1) & 31;
                int nt  = (idx >> 6) & 7;
                int ktl = (idx >> 9) & 3;
                int jl  = ktl * 16 + (ln & 3) * 2 + r * 8;
                int e   = nt * 8 + (ln >> 2);
                uint16_t h0 = *(const uint16_t*)(smem + BOUNCE + jl * ROWB + e * 2);
                uint16_t h1 = *(const uint16_t*)(smem + BOUNCE + (jl + 1) * ROWB + e * 2);
                uint32_t word = (uint32_t)h0 | ((uint32_t)h1 << 16);
                int ktg = (prev_j0 >> 4) + ktl;
                Ub[((ktg * 8 + nt) * 32 + ln) * 2 + r] = word;
            }
        }
        {
            const float* rcin = rc + ((size_t)bk * C_ + j0) * E_;
            #pragma unroll
            for (int it = 0; it < 4; it++) {
                int idx = it * 256 + t;
                int r  = idx >> 4;
                int e0 = (idx & 15) * 4;
                float4 v = *(const float4*)&rcin[(size_t)r * E_ + e0];
                int mt = r >> 4, kt = e0 >> 4;
                int reg = ((r >> 3) & 1) | (((e0 >> 3) & 1) << 1);
                int lp  = (r & 7) * 4 + ((e0 & 7) >> 1);
                uint2 w;
                w.x = pack_h2(v.x, v.y);
                w.y = pack_h2(v.z, v.w);
                *(uint2*)(smem + INF + (mt * 4 + kt) * TILES + reg * REGS + lp * 4) = w;
            }
        }
        __syncthreads();

        // ---- Layer 1 ----
        {
            float d[2][4][4];
            const float* Pp = P_scratch + (size_t)(b * C_ + j0) * H_;
            #pragma unroll
            for (int mtl = 0; mtl < 2; mtl++) {
                int r0 = wm * 32 + mtl * 16 + (lane >> 2);
                #pragma unroll
                for (int ntl = 0; ntl < 4; ntl++) {
                    int col = wn * 32 + ntl * 8 + (lane & 3) * 2;
                    float2 p0 = *(const float2*)&Pp[(size_t)r0 * H_ + col];
                    float2 p1 = *(const float2*)&Pp[(size_t)(r0 + 8) * H_ + col];
                    d[mtl][ntl][0] = p0.x; d[mtl][ntl][1] = p0.y;
                    d[mtl][ntl][2] = p1.x; d[mtl][ntl][3] = p1.y;
                }
            }
            #pragma unroll
            for (int kt = 0; kt < 4; kt++) {
                uint32_t a[2][4];
                #pragma unroll
                for (int mtl = 0; mtl < 2; mtl++) {
                    const char* base = smem + INF + ((wm * 2 + mtl) * 4 + kt) * TILES + lane * 4;
                    a[mtl][0] = *(const uint32_t*)(base);
                    a[mtl][1] = *(const uint32_t*)(base + REGS);
                    a[mtl][2] = *(const uint32_t*)(base + 2 * REGS);
                    a[mtl][3] = *(const uint32_t*)(base + 3 * REGS);
                }
                #pragma unroll
                for (int ntl = 0; ntl < 4; ntl++) {
                    int nt = wn * 4 + ntl;
                    uint2 bv = *(const uint2*)(smem + W1F + ((kt * 16 + nt) * 32 + lane) * 8);
                    uint32_t bw[2] = {bv.x, bv.y};
                    #pragma unroll
                    for (int mtl = 0; mtl < 2; mtl++) mma_f16(d[mtl][ntl], a[mtl], bw);
                }
            }
            #pragma unroll
            for (int mtl = 0; mtl < 2; mtl++) {
                int mt2 = wm * 2 + mtl;
                int lp  = (lane >> 2) * 4 + (lane & 3);
                #pragma unroll
                for (int ntl = 0; ntl < 4; ntl++) {
                    int kt2 = wn * 2 + (ntl >> 1);
                    int rlo = (ntl & 1) * 2;
                    const char* fb = smem + H1F + (mt2 * 8 + kt2) * TILES + lp * 4;
                    *(uint32_t*)(fb + rlo * REGS) =
                        pack_h2(fmaxf(d[mtl][ntl][0], 0.0f), fmaxf(d[mtl][ntl][1], 0.0f));
                    *(uint32_t*)(fb + (rlo + 1) * REGS) =
                        pack_h2(fmaxf(d[mtl][ntl][2], 0.0f), fmaxf(d[mtl][ntl][3], 0.0f));
                }
            }
        }
        __syncthreads();

        // ---- Layer 2 ----
        {
            float d[2][4][4];
            #pragma unroll
            for (int mtl = 0; mtl < 2; mtl++)
                #pragma unroll
                for (int ntl = 0; ntl < 4; ntl++) {
                    int col = wn * 32 + ntl * 8 + (lane & 3) * 2;
                    float2 bb = *(const float2*)(smem + B2S + col * 4);
                    d[mtl][ntl][0] = bb.x; d[mtl][ntl][1] = bb.y;
                    d[mtl][ntl][2] = bb.x; d[mtl][ntl][3] = bb.y;
                }
            #pragma unroll
            for (int kt = 0; kt < 8; kt++) {
                uint32_t a[2][4];
                #pragma unroll
                for (int mtl = 0; mtl < 2; mtl++) {
                    const char* base = smem + H1F + ((wm * 2 + mtl) * 8 + kt) * TILES + lane * 4;
                    a[mtl][0] = *(const uint32_t*)(base);
                    a[mtl][1] = *(const uint32_t*)(base + REGS);
                    a[mtl][2] = *(const uint32_t*)(base + 2 * REGS);
                    a[mtl][3] = *(const uint32_t*)(base + 3 * REGS);
                }
                #pragma unroll
                for (int ntl = 0; ntl < 4; ntl++) {
                    int nt = wn * 4 + ntl;
                    uint2 bv = *(const uint2*)(smem + W2F + ((kt * 16 + nt) * 32 + lane) * 8);
                    uint32_t bw[2] = {bv.x, bv.y};
                    #pragma unroll
                    for (int mtl = 0; mtl < 2; mtl++) mma_f16(d[mtl][ntl], a[mtl], bw);
                }
            }
            #pragma unroll
            for (int mtl = 0; mtl < 2; mtl++) {
                int mt2 = wm * 2 + mtl;
                int lp  = (lane >> 2) * 4 + (lane & 3);
                #pragma unroll
                for (int ntl = 0; ntl < 4; ntl++) {
                    int kt2 = wn * 2 + (ntl >> 1);
                    int rlo = (ntl & 1) * 2;
                    const char* fb = smem + H2F + (mt2 * 8 + kt2) * TILES + lp * 4;
                    *(uint32_t*)(fb + rlo * REGS) =
                        pack_h2(fmaxf(d[mtl][ntl][0], 0.0f), fmaxf(d[mtl][ntl][1], 0.0f));
                    *(uint32_t*)(fb + (rlo + 1) * REGS) =
                        pack_h2(fmaxf(d[mtl][ntl][2], 0.0f), fmaxf(d[mtl][ntl][3], 0.0f));
                }
            }
        }
        __syncthreads();

        // ---- Layer 3 ----
        {
            float d[2][2][4];
            #pragma unroll
            for (int mtl = 0; mtl < 2; mtl++)
                #pragma unroll
                for (int ntl = 0; ntl < 2; ntl++) {
                    int e = wn * 16 + ntl * 8 + (lane & 3) * 2;
                    float2 bb = *(const float2*)(smem + B3S + e * 4);
                    d[mtl][ntl][0] = bb.x; d[mtl][ntl][1] = bb.y;
                    d[mtl][ntl][2] = bb.x; d[mtl][ntl][3] = bb.y;
                }
            #pragma unroll
            for (int kt = 0; kt < 8; kt++) {
                uint32_t a[2][4];
                #pragma unroll
                for (int mtl = 0; mtl < 2; mtl++) {
                    const char* base = smem + H2F + ((wm * 2 + mtl) * 8 + kt) * TILES + lane * 4;
                    a[mtl][0] = *(const uint32_t*)(base);
                    a[mtl][1] = *(const uint32_t*)(base + REGS);
                    a[mtl][2] = *(const uint32_t*)(base + 2 * REGS);
                    a[mtl][3] = *(const uint32_t*)(base + 3 * REGS);
                }
                #pragma unroll
                for (int ntl = 0; ntl < 2; ntl++) {
                    int nt = wn * 2 + ntl;
                    uint2 bv = *(const uint2*)(smem + W3F + ((kt * 8 + nt) * 32 + lane) * 8);
                    uint32_t bw[2] = {bv.x, bv.y};
                    #pragma unroll
                    for (int mtl = 0; mtl < 2; mtl++) mma_f16(d[mtl][ntl], a[mtl], bw);
                }
            }
            #pragma unroll
            for (int mtl = 0; mtl < 2; mtl++) {
                int row = wm * 32 + mtl * 16 + (lane >> 2);
                #pragma unroll
                for (int ntl = 0; ntl < 2; ntl++) {
                    int e = wn * 16 + ntl * 8 + (lane & 3) * 2;
                    *(uint32_t*)(smem + BOUNCE + row * ROWB + e * 2) =
                        pack_h2(d[mtl][ntl][0], d[mtl][ntl][1]);
                    *(uint32_t*)(smem + BOUNCE + (row + 8) * ROWB + e * 2) =
                        pack_h2(d[mtl][ntl][2], d[mtl][ntl][3]);
                }
            }
        }
        __syncthreads();

        prev_bk = bk; prev_j0 = j0;
    }

    if (prev_bk >= 0) {
        uint32_t* Ub = U_scratch + (size_t)prev_bk * 8192;
        #pragma unroll
        for (int w = 0; w < 8; w++) {
            int idx = w * 256 + t;
            int r   = idx & 1;
            int ln  = (idx >> 1) & 31;
            int nt  = (idx >> 6) & 7;
            int ktl = (idx >> 9) & 3;
            int jl  = ktl * 16 + (ln & 3) * 2 + r * 8;
            int e   = nt * 8 + (ln >> 2);
            uint16_t h0 = *(const uint16_t*)(smem + BOUNCE + jl * ROWB + e * 2);
            uint16_t h1 = *(const uint16_t*)(smem + BOUNCE + (jl + 1) * ROWB + e * 2);
            uint32_t word = (uint32_t)h0 | ((uint32_t)h1 << 16);
            int ktg = (prev_j0 >> 4) + ktl;
            Ub[((ktg * 8 + nt) * 32 + ln) * 2 + r] = word;
        }
    }
}

// ---------------------------------------------------------------------------
// Kernel 3: fp16 mma attention, warp grid (wm2, wn4), k processed in PAIRS:
// one A-fragment load feeds mma for two k's (both B tiles resident).
// No K-split, no reduction. Synchronous per-pair B loads (hidden by 2 CTA/SM).
// ---------------------------------------------------------------------------
#define AT_A  0
#define AT_B0 32768
#define AT_B1 65536
#define AT_SMEM 98304

__global__ void __launch_bounds__(256, 2)
attn_mma_kernel(const float* __restrict__ rc, const float* __restrict__ rq,
                float* __restrict__ out) {
    extern __shared__ char smem[];
    const uint32_t smem_base = smem_u32(smem);
    const int t = threadIdx.x;
    const int x = blockIdx.x;
    const int kg  = x & 31;
    const int Mq  = (x >> 5) & 3;
    const int map = (x >> 7) & 1;
    const int b   = x >> 8;

    const int wid  = t >> 5;
    const int lane = t & 31;
    const int wm = wid >> 2;       // 2 M-groups of 32 rows
    const int wn = wid & 3;        // 4 N-groups of 16 cols

    const int k0 = kg * 8;

    // ---- async-stage A + B(k0) + B(k0+1) ----
    {
        const char* srcA  = (const char*)(ATT_frag + ((size_t)((map * 4 + b) * 4 + Mq)) * 8192);
        const char* srcB0 = (const char*)(U_scratch + ((size_t)(b * C_ + k0)) * 8192);
        const char* srcB1 = (const char*)(U_scratch + ((size_t)(b * C_ + k0 + 1)) * 8192);
        #pragma unroll
        for (int it = 0; it < 8; it++) {
            int o = (it * 256 + t) * 16;
            cp_async16(smem_base + AT_A + o, srcA + o);
        }
        #pragma unroll
        for (int it = 0; it < 8; it++) {
            int o = (it * 256 + t) * 16;
            cp_async16(smem_base + AT_B0 + o, srcB0 + o);
        }
        #pragma unroll
        for (int it = 0; it < 8; it++) {
            int o = (it * 256 + t) * 16;
            cp_async16(smem_base + AT_B1 + o, srcB1 + o);
        }
        cp_commit();
    }
    cp_wait0();
    __syncthreads();

    float* outbase = out + (map ? (size_t)B_ * C_ * C_ * E_ : 0);
    const float* residbase = map ? rq : rc;

    #pragma unroll 1
    for (int p = 0; p < 4; p++) {
        const int ka = k0 + 2 * p;

        // ---- mainloop: one A load per kt feeds both k's ----
        float d0[2][2][4], d1[2][2][4];
        #pragma unroll
        for (int i0 = 0; i0 < 2; i0++)
            #pragma unroll
            for (int i1 = 0; i1 < 2; i1++)
                #pragma unroll
                for (int i2 = 0; i2 < 4; i2++) { d0[i0][i1][i2] = 0.0f; d1[i0][i1][i2] = 0.0f; }

        #pragma unroll 4
        for (int kt = 0; kt < 16; kt++) {
            uint32_t a[2][4];
            #pragma unroll
            for (int mtl = 0; mtl < 2; mtl++) {
                const char* base = smem + AT_A + ((wm * 2 + mtl) * 16 + kt) * TILEA + lane * 4;
                a[mtl][0] = *(const uint32_t*)(base);
                a[mtl][1] = *(const uint32_t*)(base + REGA);
                a[mtl][2] = *(const uint32_t*)(base + 2 * REGA);
                a[mtl][3] = *(const uint32_t*)(base + 3 * REGA);
            }
            uint32_t bw0[2][2], bw1[2][2];
            #pragma unroll
            for (int ntl = 0; ntl < 2; ntl++) {
                int nt = wn * 2 + ntl;
                uint2 v0 = *(const uint2*)(smem + AT_B0 + ((kt * 8 + nt) * 32 + lane) * 8);
                uint2 v1 = *(const uint2*)(smem + AT_B1 + ((kt * 8 + nt) * 32 + lane) * 8);
                bw0[ntl][0] = v0.x; bw0[ntl][1] = v0.y;
                bw1[ntl][0] = v1.x; bw1[ntl][1] = v1.y;
            }
            #pragma unroll
            for (int mtl = 0; mtl < 2; mtl++)
                #pragma unroll
                for (int ntl = 0; ntl < 2; ntl++) {
                    mma_f16(d0[mtl][ntl], a[mtl], bw0[ntl]);
                    mma_f16(d1[mtl][ntl], a[mtl], bw1[ntl]);
                }
        }

        // ---- epilogue for both k's (all 8 warps) ----
        #pragma unroll
        for (int kq = 0; kq < 2; kq++) {
            const int k = ka + kq;
            float (*dd)[2][4] = kq ? d1 : d0;
            const float* resid = residbase + ((size_t)(b * C_ + k) * C_) * E_;
            float* o = outbase + ((size_t)(b * C_ + k) * C_) * E_;
            #pragma unroll
            for (int mtl = 0; mtl < 2; mtl++) {
                int row = Mq * 64 + wm * 32 + mtl * 16 + (lane >> 2);
                #pragma unroll
                for (int ntl = 0; ntl < 2; ntl++) {
                    int e = wn * 16 + ntl * 8 + (lane & 3) * 2;
                    float2 rA = *(const float2*)&resid[(size_t)row * E_ + e];
                    float2 rB = *(const float2*)&resid[(size_t)(row + 8) * E_ + e];
                    float2 oA, oB;
                    oA.x = rA.x - ALPHA * dd[mtl][ntl][0];
                    oA.y = rA.y - ALPHA * dd[mtl][ntl][1];
                    oB.x = rB.x - ALPHA * dd[mtl][ntl][2];
                    oB.y = rB.y - ALPHA * dd[mtl][ntl][3];
                    *(float2*)&o[(size_t)row * E_ + e]       = oA;
                    *(float2*)&o[(size_t)(row + 8) * E_ + e] = oB;
                }
            }
        }

        // ---- load next pair's B tiles (buffers free only after all reads) ----
        if (p < 3) {
            __syncthreads();   // everyone done reading B0/B1
            const char* srcB0 = (const char*)(U_scratch + ((size_t)(b * C_ + ka + 2)) * 8192);
            const char* srcB1 = (const char*)(U_scratch + ((size_t)(b * C_ + ka + 3)) * 8192);
            #pragma unroll
            for (int it = 0; it < 8; it++) {
                int o = (it * 256 + t) * 16;
                cp_async16(smem_base + AT_B0 + o, srcB0 + o);
            }
            #pragma unroll
            for (int it = 0; it < 8; it++) {
                int o = (it * 256 + t) * 16;
                cp_async16(smem_base + AT_B1 + o, srcB1 + o);
            }
            cp_commit();
            cp_wait0();
            __syncthreads();
        }
    }
}

// ---------------------------------------------------------------------------
// Launch
// ---------------------------------------------------------------------------
extern "C" void kernel_launch(void* const* d_in, const int* in_sizes, int n_in,
                              void* d_out, int out_size) {
    const float* x    = (const float*)d_in[0];
    const float* y    = (const float*)d_in[1];
    const float* rc   = (const float*)d_in[2];
    const float* rq   = (const float*)d_in[3];
    const float* attc = (const float*)d_in[4];
    const float* attq = (const float*)d_in[5];
    const float* W1   = (const float*)d_in[6];
    const float* b1   = (const float*)d_in[7];
    const float* W2   = (const float*)d_in[8];
    const float* b2   = (const float*)d_in[9];
    const float* W3   = (const float*)d_in[10];
    const float* b3   = (const float*)d_in[11];
    float* out = (float*)d_out;

    cudaFuncSetAttribute(mlp_tc_kernel,   cudaFuncAttributeMaxDynamicSharedMemorySize, MLP_SMEM_B);
    cudaFuncSetAttribute(attn_mma_kernel, cudaFuncAttributeMaxDynamicSharedMemorySize, AT_SMEM);

    p_kernel<<<B_ * C_, H_>>>(x, y, W1, b1, attc, attq);
    mlp_tc_kernel<<<296, 256, MLP_SMEM_B>>>(rc, W1, b2, W2, W3, b3);
    attn_mma_kernel<<<1024, 256, AT_SMEM>>>(rc, rq, out);
}